// round 10
// baseline (speedup 1.0000x reference)
#include <cuda_runtime.h>
#include <math.h>
#include <stdint.h>

#define BS     32
#define GRID_N 2704
#define A_N    3
#define CH     85
#define VDIM   1024
#define HDIM   512
#define SEL    32
#define ROWS   (BS * SEL)          // 1024 flattened rows
#define EPSF   1e-8f

// ---------------- device scratch (static, no allocation) ----------------
__device__ int      g_idx[BS * SEL];
__device__ uint32_t g_iselH[(size_t)ROWS * VDIM];
__device__ uint32_t g_iselL[(size_t)ROWS * VDIM];
__device__ float    g_vis[(size_t)ROWS * HDIM];
__device__ float    g_w[ROWS * 2];
__device__ float    g_vis2[(size_t)ROWS * HDIM];
__device__ float    g_lang[BS * HDIM];
__device__ float    g_ln[BS];
// presplit weights
__device__ uint32_t g_WvsH[(size_t)VDIM * HDIM];
__device__ uint32_t g_WvsL[(size_t)VDIM * HDIM];
__device__ uint32_t g_WvpH[HDIM * HDIM];
__device__ uint32_t g_WvpL[HDIM * HDIM];
__device__ uint32_t g_WtgH[HDIM * HDIM];
__device__ uint32_t g_WtgL[HDIM * HDIM];
// presplit scaled activations for gemm2
__device__ uint32_t g_XH[(size_t)ROWS * HDIM];
__device__ uint32_t g_XL[(size_t)ROWS * HDIM];
__device__ uint32_t g_YH[(size_t)ROWS * HDIM];
__device__ uint32_t g_YL[(size_t)ROWS * HDIM];

// ---------------- tf32 helpers --------------------------------------------
__device__ __forceinline__ uint32_t f2tf(float x) {
    uint32_t r;
    asm("cvt.rna.tf32.f32 %0, %1;" : "=r"(r) : "f"(x));
    return r;
}
__device__ __forceinline__ void split_tf(float x, uint32_t& hi, uint32_t& lo) {
    hi = f2tf(x);
    lo = f2tf(x - __uint_as_float(hi));
}
__device__ __forceinline__ void split4(float4 v, uint4& h, uint4& l) {
    split_tf(v.x, h.x, l.x);
    split_tf(v.y, h.y, l.y);
    split_tf(v.z, h.z, l.z);
    split_tf(v.w, h.w, l.w);
}
__device__ __forceinline__ void mma8(float d[4], const uint32_t a[4], const uint32_t b[2]) {
    asm volatile(
        "mma.sync.aligned.m16n8k8.row.col.f32.tf32.tf32.f32 "
        "{%0,%1,%2,%3}, {%4,%5,%6,%7}, {%8,%9}, {%0,%1,%2,%3};"
        : "+f"(d[0]), "+f"(d[1]), "+f"(d[2]), "+f"(d[3])
        : "r"(a[0]), "r"(a[1]), "r"(a[2]), "r"(a[3]), "r"(b[0]), "r"(b[1]));
}

// ---------------- K0: generic weight split (float4 granular) -------------
__global__ void split_kernel(const float* __restrict__ src, uint32_t* __restrict__ h,
                             uint32_t* __restrict__ l, int n4) {
    int i = blockIdx.x * blockDim.x + threadIdx.x;
    if (i >= n4) return;
    float4 v = ((const float4*)src)[i];
    uint4 hh, ll;
    split4(v, hh, ll);
    ((uint4*)h)[i] = hh;
    ((uint4*)l)[i] = ll;
}

// ---------------- K1: objectness score + exact top-32 via histogram ------
__global__ void topk_kernel(const float* __restrict__ boxes) {
    int b = blockIdx.x;
    int tid = threadIdx.x;          // 256 threads
    __shared__ float sc[GRID_N];
    __shared__ int   hist[512];
    __shared__ int   s_binB, s_definite;
    __shared__ int   cnt_hi, cnt_cb, overflow;
    __shared__ int   hi_idx[SEL];
    __shared__ float cb_sc[512];
    __shared__ int   cb_idx[512];
    __shared__ int   sel[SEL];
    __shared__ float rv[8];
    __shared__ int   ri[8];

    for (int i = tid; i < 512; i += 256) hist[i] = 0;
    if (tid == 0) { cnt_hi = 0; cnt_cb = 0; overflow = 0; }
    __syncthreads();

    const float* bb = boxes + (size_t)b * GRID_N * A_N * CH;
    for (int g = tid; g < GRID_N; g += 256) {
        const float* p = bb + (size_t)g * A_N * CH;
        float s = (p[4] + p[CH + 4] + p[2 * CH + 4]) * (1.0f / 3.0f);
        sc[g] = s;
        int bin = (int)(s * 512.0f);
        bin = max(0, min(511, bin));
        atomicAdd(&hist[bin], 1);
    }
    __syncthreads();

    if (tid == 0) {
        int cum = 0, bB = 0, def = 0;
        for (int v = 511; v >= 0; v--) {
            cum += hist[v];
            if (cum >= SEL) { bB = v; def = cum - hist[v]; break; }
        }
        s_binB = bB; s_definite = def;
    }
    __syncthreads();
    int binB = s_binB;

    for (int g = tid; g < GRID_N; g += 256) {
        float s = sc[g];
        int bin = (int)(s * 512.0f);
        bin = max(0, min(511, bin));
        if (bin > binB) {
            int p = atomicAdd(&cnt_hi, 1);
            hi_idx[p] = g;
        } else if (bin == binB) {
            int p = atomicAdd(&cnt_cb, 1);
            if (p < 512) { cb_sc[p] = s; cb_idx[p] = g; }
            else overflow = 1;
        }
    }
    __syncthreads();

    if (!overflow) {
        if (tid >= 32 && (tid - 32) < s_definite) sel[tid - 32] = hi_idx[tid - 32];
        if (tid < 32) {
            int need = SEL - s_definite;
            int n = min(cnt_cb, 512);
            for (int it = 0; it < need; it++) {
                float best = -1e30f; int bi = GRID_N;
                for (int c = tid; c < n; c += 32) {
                    float v = cb_sc[c]; int gi = cb_idx[c];
                    if (v > best || (v == best && gi < bi)) { best = v; bi = gi; }
                }
                #pragma unroll
                for (int o = 16; o; o >>= 1) {
                    float ov = __shfl_down_sync(0xffffffffu, best, o);
                    int   oi = __shfl_down_sync(0xffffffffu, bi, o);
                    if (ov > best || (ov == best && oi < bi)) { best = ov; bi = oi; }
                }
                bi = __shfl_sync(0xffffffffu, bi, 0);
                if (tid == 0) sel[s_definite + it] = bi;
                for (int c = tid; c < n; c += 32)
                    if (cb_idx[c] == bi) cb_sc[c] = -1e30f;
                __syncwarp();
            }
        }
    }
    __syncthreads();

    if (overflow) {
        for (int it = 0; it < SEL; it++) {
            float best = -1e30f;
            int   bi = GRID_N;
            for (int g = tid; g < GRID_N; g += 256) {
                float v = sc[g];
                if (v > best) { best = v; bi = g; }
            }
            #pragma unroll
            for (int o = 16; o; o >>= 1) {
                float ov = __shfl_down_sync(0xffffffffu, best, o);
                int   oi = __shfl_down_sync(0xffffffffu, bi, o);
                if (ov > best || (ov == best && oi < bi)) { best = ov; bi = oi; }
            }
            if ((tid & 31) == 0) { rv[tid >> 5] = best; ri[tid >> 5] = bi; }
            __syncthreads();
            if (tid == 0) {
                float B = rv[0]; int BI = ri[0];
                for (int w = 1; w < 8; w++)
                    if (rv[w] > B || (rv[w] == B && ri[w] < BI)) { B = rv[w]; BI = ri[w]; }
                sel[it] = BI;
                sc[BI] = -1e30f;
            }
            __syncthreads();
        }
    }

    if (tid == 0) {
        for (int i = 1; i < SEL; i++) {
            int v = sel[i], j = i - 1;
            while (j >= 0 && sel[j] > v) { sel[j + 1] = sel[j]; j--; }
            sel[j + 1] = v;
        }
        for (int i = 0; i < SEL; i++) g_idx[b * SEL + i] = sel[i];
    }
}

// ---------------- K2: gather + split selected feature columns ------------
__global__ void gather_kernel(const float* __restrict__ xfeat) {
    int row = blockIdx.x;           // b*SEL + s
    int b = row >> 5;
    int g = g_idx[row];
    const float* src = xfeat + (size_t)b * VDIM * GRID_N + g;
    uint32_t* dh = g_iselH + (size_t)row * VDIM;
    uint32_t* dl = g_iselL + (size_t)row * VDIM;
    for (int v = threadIdx.x; v < VDIM; v += blockDim.x) {
        float x = __ldg(&src[(size_t)v * GRID_N]);
        uint32_t h, l;
        split_tf(x, h, l);
        dh[v] = h;
        dl[v] = l;
    }
}

// ---------------- K3: vis = isel @ W_vs + b_vs (3xTF32, zero-CVT) --------
// Tile 32(M)x64(N), BK=32, 256 threads = 8 warps (2m x 4n), warp m16n16.
// A smem: hi/lo planes [m][k] stride 36. B smem: hi/lo [k][n], swizzle
// n ^ ((k&3)*8). Inner loop: pure LDS.32 + MMA.
#define G1_BK 32
#define G1_NT (VDIM / G1_BK)
#define X1ST 36
__global__ __launch_bounds__(256) void gemm1_kernel(const float* __restrict__ bias) {
    int mBase = blockIdx.y * 32;
    int nBase = blockIdx.x * 64;
    int tid = threadIdx.x;
    int warp = tid >> 5, lane = tid & 31;
    int gid = lane >> 2, tig = lane & 3;
    int wm = (warp & 1) * 16, wn = (warp >> 1) * 16;

    __shared__ __align__(16) uint32_t AsH[2][32 * X1ST];
    __shared__ __align__(16) uint32_t AsL[2][32 * X1ST];
    __shared__ __align__(16) uint32_t WsH[2][G1_BK * 64];
    __shared__ __align__(16) uint32_t WsL[2][G1_BK * 64];

    int a_m = tid >> 3;             // 0..31
    int a_k = (tid & 7) * 4;        // 0..28
    int w_k = tid >> 4;             // 0..15 (k rows w_k, w_k+16)
    int w_n = (tid & 15) * 4;

    const uint32_t* AbH = g_iselH + (size_t)mBase * VDIM;
    const uint32_t* AbL = g_iselL + (size_t)mBase * VDIM;

    uint4 rAh, rAl, rWh[2], rWl[2];
    rAh = *(const uint4*)&AbH[(size_t)a_m * VDIM + a_k];
    rAl = *(const uint4*)&AbL[(size_t)a_m * VDIM + a_k];
    #pragma unroll
    for (int i = 0; i < 2; i++) {
        size_t off = (size_t)(w_k + i * 16) * HDIM + nBase + w_n;
        rWh[i] = *(const uint4*)&g_WvsH[off];
        rWl[i] = *(const uint4*)&g_WvsL[off];
    }

    *(uint4*)&AsH[0][a_m * X1ST + a_k] = rAh;
    *(uint4*)&AsL[0][a_m * X1ST + a_k] = rAl;
    #pragma unroll
    for (int i = 0; i < 2; i++) {
        int k = w_k + i * 16;
        int off = k * 64 + (w_n ^ ((k & 3) * 8));
        *(uint4*)&WsH[0][off] = rWh[i];
        *(uint4*)&WsL[0][off] = rWl[i];
    }
    __syncthreads();

    float acc[2][4];
    #pragma unroll
    for (int j = 0; j < 2; j++)
        #pragma unroll
        for (int r = 0; r < 4; r++) acc[j][r] = 0.f;

    for (int t = 0; t < G1_NT; t++) {
        int cur = t & 1;
        int k0n = (t + 1) * G1_BK;
        if (t + 1 < G1_NT) {
            rAh = *(const uint4*)&AbH[(size_t)a_m * VDIM + k0n + a_k];
            rAl = *(const uint4*)&AbL[(size_t)a_m * VDIM + k0n + a_k];
            #pragma unroll
            for (int i = 0; i < 2; i++) {
                size_t off = (size_t)(k0n + w_k + i * 16) * HDIM + nBase + w_n;
                rWh[i] = *(const uint4*)&g_WvsH[off];
                rWl[i] = *(const uint4*)&g_WvsL[off];
            }
        }
        #pragma unroll
        for (int kb = 0; kb < G1_BK; kb += 8) {
            uint32_t ah[4], al[4];
            ah[0] = AsH[cur][(wm + gid) * X1ST + kb + tig];
            ah[1] = AsH[cur][(wm + gid + 8) * X1ST + kb + tig];
            ah[2] = AsH[cur][(wm + gid) * X1ST + kb + tig + 4];
            ah[3] = AsH[cur][(wm + gid + 8) * X1ST + kb + tig + 4];
            al[0] = AsL[cur][(wm + gid) * X1ST + kb + tig];
            al[1] = AsL[cur][(wm + gid + 8) * X1ST + kb + tig];
            al[2] = AsL[cur][(wm + gid) * X1ST + kb + tig + 4];
            al[3] = AsL[cur][(wm + gid + 8) * X1ST + kb + tig + 4];
            #pragma unroll
            for (int j = 0; j < 2; j++) {
                int n0 = wn + j * 8;
                int sw = (n0 + gid) ^ (tig * 8);
                uint32_t bh[2], bl[2];
                bh[0] = WsH[cur][(kb + tig) * 64 + sw];
                bh[1] = WsH[cur][(kb + tig + 4) * 64 + sw];
                bl[0] = WsL[cur][(kb + tig) * 64 + sw];
                bl[1] = WsL[cur][(kb + tig + 4) * 64 + sw];
                mma8(acc[j], ah, bh);
                mma8(acc[j], ah, bl);
                mma8(acc[j], al, bh);
            }
        }
        if (t + 1 < G1_NT) {
            int nx = cur ^ 1;
            *(uint4*)&AsH[nx][a_m * X1ST + a_k] = rAh;
            *(uint4*)&AsL[nx][a_m * X1ST + a_k] = rAl;
            #pragma unroll
            for (int i = 0; i < 2; i++) {
                int k = w_k + i * 16;
                int off = k * 64 + (w_n ^ ((k & 3) * 8));
                *(uint4*)&WsH[nx][off] = rWh[i];
                *(uint4*)&WsL[nx][off] = rWl[i];
            }
        }
        __syncthreads();
    }

    int row0 = mBase + wm + gid;
    #pragma unroll
    for (int j = 0; j < 2; j++) {
        int col = nBase + wn + j * 8 + 2 * tig;
        float b0 = bias[col], b1 = bias[col + 1];
        float2 o0 = make_float2(acc[j][0] + b0, acc[j][1] + b1);
        float2 o1 = make_float2(acc[j][2] + b0, acc[j][3] + b1);
        *(float2*)&g_vis[(size_t)row0 * HDIM + col] = o0;
        *(float2*)&g_vis[(size_t)(row0 + 8) * HDIM + col] = o1;
    }
}

// ---------------- K4: gate logits (2 warps per row) ----------------------
__global__ __launch_bounds__(256) void wsoft_kernel(const float* __restrict__ tag,
                                                    const float* __restrict__ pos,
                                                    const float* __restrict__ Wsoft,
                                                    const float* __restrict__ bsoft) {
    int tid = threadIdx.x;
    int w = tid >> 5, lane = tid & 31;
    int rb = blockIdx.x * 4;                 // 256 blocks, 4 rows each
    int r = rb + (w >> 1);
    int half = w & 1;
    __shared__ float pl[8][2];

    const float4* v = (const float4*)(g_vis + (size_t)r * HDIM);
    const float4* t = (const float4*)(tag + (size_t)r * HDIM);
    const float4* p = (const float4*)(pos + (size_t)r * HDIM);
    const float4* Wq = (const float4*)Wsoft;
    float l0 = 0.f, l1 = 0.f;
    #pragma unroll
    for (int i = 0; i < 2; i++) {
        int h4 = half * 64 + i * 32 + lane;
        float4 a = v[h4], c = t[h4], e = p[h4];
        float s0 = a.x + c.x + e.x, s1 = a.y + c.y + e.y;
        float s2 = a.z + c.z + e.z, s3 = a.w + c.w + e.w;
        float4 w01 = Wq[h4 * 2], w23 = Wq[h4 * 2 + 1];
        l0 += s0 * w01.x + s1 * w01.z + s2 * w23.x + s3 * w23.z;
        l1 += s0 * w01.y + s1 * w01.w + s2 * w23.y + s3 * w23.w;
    }
    #pragma unroll
    for (int o = 16; o; o >>= 1) {
        l0 += __shfl_xor_sync(0xffffffffu, l0, o);
        l1 += __shfl_xor_sync(0xffffffffu, l1, o);
    }
    if (lane == 0) { pl[w][0] = l0; pl[w][1] = l1; }
    __syncthreads();
    if (tid < 4) {
        int rr = rb + tid;
        float L0 = pl[tid * 2][0] + pl[tid * 2 + 1][0];
        float L1 = pl[tid * 2][1] + pl[tid * 2 + 1][1];
        L0 = (L0 + bsoft[0]) / 0.03f;
        L1 = (L1 + bsoft[1]) / 0.03f;
        float m = fmaxf(L0, L1);
        float lse = m + logf(expf(L0 - m) + expf(L1 - m));
        g_w[2 * rr + 0] = L0 - lse;
        g_w[2 * rr + 1] = L1 - lse;
    }
}

// ---------------- K4b: scale by gates + split (X = vis*w0, Y = tag*w1) ---
__global__ __launch_bounds__(256) void scale_split_kernel(const float* __restrict__ tag) {
    int i = blockIdx.x * 256 + threadIdx.x;      // float4 index, ROWS*HDIM/4 total
    int row = i >> 7;                            // HDIM/4 = 128
    float w0 = g_w[2 * row], w1 = g_w[2 * row + 1];
    float4 v = ((const float4*)g_vis)[i];
    float4 t = ((const float4*)tag)[i];
    v.x *= w0; v.y *= w0; v.z *= w0; v.w *= w0;
    t.x *= w1; t.y *= w1; t.z *= w1; t.w *= w1;
    uint4 h, l;
    split4(v, h, l);
    ((uint4*)g_XH)[i] = h;
    ((uint4*)g_XL)[i] = l;
    split4(t, h, l);
    ((uint4*)g_YH)[i] = h;
    ((uint4*)g_YL)[i] = l;
}

// ---------------- K5: vis2 dual GEMM (3xTF32, zero-CVT) ------------------
// Tile 32x64, BK=16, 256 threads = 8 warps, warp m16n16.
#define G2_BK 16
#define G2_NT (HDIM / G2_BK)
#define A2ST 20
__global__ __launch_bounds__(256) void gemm2_kernel(
    const float* __restrict__ bvp, const float* __restrict__ btg,
    const float* __restrict__ pos) {
    int mBase = blockIdx.y * 32;
    int nBase = blockIdx.x * 64;
    int tid = threadIdx.x;
    int warp = tid >> 5, lane = tid & 31;
    int gid = lane >> 2, tig = lane & 3;
    int wm = (warp & 1) * 16, wn = (warp >> 1) * 16;

    __shared__ __align__(16) uint32_t XsH[2][32 * A2ST];
    __shared__ __align__(16) uint32_t XsL[2][32 * A2ST];
    __shared__ __align__(16) uint32_t YsH[2][32 * A2ST];
    __shared__ __align__(16) uint32_t YsL[2][32 * A2ST];
    __shared__ __align__(16) uint32_t WsH[2][G2_BK * 64];
    __shared__ __align__(16) uint32_t WsL[2][G2_BK * 64];
    __shared__ __align__(16) uint32_t VsH[2][G2_BK * 64];
    __shared__ __align__(16) uint32_t VsL[2][G2_BK * 64];

    // A-side: threads 0-127 handle X, 128-255 handle Y (uint4 H+L each)
    int ahalf = tid >> 7;
    int at = tid & 127;
    int a_m = at >> 2;              // 0..31
    int a_k = (at & 3) * 4;         // 0..12
    // W/V: one uint4 per plane per thread, w_k 0..15 covers BK=16
    int w_k = tid >> 4;
    int w_n = (tid & 15) * 4;

    const uint32_t* AH = (ahalf ? g_YH : g_XH) + (size_t)mBase * HDIM;
    const uint32_t* AL = (ahalf ? g_YL : g_XL) + (size_t)mBase * HDIM;

    uint4 rSh, rSl, rWh, rWl, rVh, rVl;
    rSh = *(const uint4*)&AH[(size_t)a_m * HDIM + a_k];
    rSl = *(const uint4*)&AL[(size_t)a_m * HDIM + a_k];
    {
        size_t off = (size_t)w_k * HDIM + nBase + w_n;
        rWh = *(const uint4*)&g_WvpH[off];
        rWl = *(const uint4*)&g_WvpL[off];
        rVh = *(const uint4*)&g_WtgH[off];
        rVl = *(const uint4*)&g_WtgL[off];
    }

    {
        uint32_t* dH = (ahalf ? YsH[0] : XsH[0]) + a_m * A2ST + a_k;
        uint32_t* dL = (ahalf ? YsL[0] : XsL[0]) + a_m * A2ST + a_k;
        *(uint4*)dH = rSh;
        *(uint4*)dL = rSl;
    }
    {
        int off = w_k * 64 + (w_n ^ ((w_k & 3) * 8));
        *(uint4*)&WsH[0][off] = rWh;
        *(uint4*)&WsL[0][off] = rWl;
        *(uint4*)&VsH[0][off] = rVh;
        *(uint4*)&VsL[0][off] = rVl;
    }
    __syncthreads();

    float acc[2][4];
    #pragma unroll
    for (int j = 0; j < 2; j++)
        #pragma unroll
        for (int r = 0; r < 4; r++) acc[j][r] = 0.f;

    for (int t = 0; t < G2_NT; t++) {
        int cur = t & 1;
        int k0n = (t + 1) * G2_BK;
        if (t + 1 < G2_NT) {
            rSh = *(const uint4*)&AH[(size_t)a_m * HDIM + k0n + a_k];
            rSl = *(const uint4*)&AL[(size_t)a_m * HDIM + k0n + a_k];
            size_t off = (size_t)(k0n + w_k) * HDIM + nBase + w_n;
            rWh = *(const uint4*)&g_WvpH[off];
            rWl = *(const uint4*)&g_WvpL[off];
            rVh = *(const uint4*)&g_WtgH[off];
            rVl = *(const uint4*)&g_WtgL[off];
        }
        #pragma unroll
        for (int kb = 0; kb < G2_BK; kb += 8) {
            uint32_t xh[4], xl[4], yh[4], yl[4];
            xh[0] = XsH[cur][(wm + gid) * A2ST + kb + tig];
            xh[1] = XsH[cur][(wm + gid + 8) * A2ST + kb + tig];
            xh[2] = XsH[cur][(wm + gid) * A2ST + kb + tig + 4];
            xh[3] = XsH[cur][(wm + gid + 8) * A2ST + kb + tig + 4];
            xl[0] = XsL[cur][(wm + gid) * A2ST + kb + tig];
            xl[1] = XsL[cur][(wm + gid + 8) * A2ST + kb + tig];
            xl[2] = XsL[cur][(wm + gid) * A2ST + kb + tig + 4];
            xl[3] = XsL[cur][(wm + gid + 8) * A2ST + kb + tig + 4];
            yh[0] = YsH[cur][(wm + gid) * A2ST + kb + tig];
            yh[1] = YsH[cur][(wm + gid + 8) * A2ST + kb + tig];
            yh[2] = YsH[cur][(wm + gid) * A2ST + kb + tig + 4];
            yh[3] = YsH[cur][(wm + gid + 8) * A2ST + kb + tig + 4];
            yl[0] = YsL[cur][(wm + gid) * A2ST + kb + tig];
            yl[1] = YsL[cur][(wm + gid + 8) * A2ST + kb + tig];
            yl[2] = YsL[cur][(wm + gid) * A2ST + kb + tig + 4];
            yl[3] = YsL[cur][(wm + gid + 8) * A2ST + kb + tig + 4];
            #pragma unroll
            for (int j = 0; j < 2; j++) {
                int n0 = wn + j * 8;
                int sw = (n0 + gid) ^ (tig * 8);
                uint32_t wh[2], wl[2], vh[2], vl[2];
                wh[0] = WsH[cur][(kb + tig) * 64 + sw];
                wh[1] = WsH[cur][(kb + tig + 4) * 64 + sw];
                wl[0] = WsL[cur][(kb + tig) * 64 + sw];
                wl[1] = WsL[cur][(kb + tig + 4) * 64 + sw];
                vh[0] = VsH[cur][(kb + tig) * 64 + sw];
                vh[1] = VsH[cur][(kb + tig + 4) * 64 + sw];
                vl[0] = VsL[cur][(kb + tig) * 64 + sw];
                vl[1] = VsL[cur][(kb + tig + 4) * 64 + sw];
                mma8(acc[j], xh, wh);
                mma8(acc[j], xh, wl);
                mma8(acc[j], xl, wh);
                mma8(acc[j], yh, vh);
                mma8(acc[j], yh, vl);
                mma8(acc[j], yl, vh);
            }
        }
        if (t + 1 < G2_NT) {
            int nx = cur ^ 1;
            uint32_t* dH = (ahalf ? YsH[nx] : XsH[nx]) + a_m * A2ST + a_k;
            uint32_t* dL = (ahalf ? YsL[nx] : XsL[nx]) + a_m * A2ST + a_k;
            *(uint4*)dH = rSh;
            *(uint4*)dL = rSl;
            int off = w_k * 64 + (w_n ^ ((w_k & 3) * 8));
            *(uint4*)&WsH[nx][off] = rWh;
            *(uint4*)&WsL[nx][off] = rWl;
            *(uint4*)&VsH[nx][off] = rVh;
            *(uint4*)&VsL[nx][off] = rVl;
        }
        __syncthreads();
    }

    int row0 = mBase + wm + gid;
    #pragma unroll
    for (int j = 0; j < 2; j++) {
        int col = nBase + wn + j * 8 + 2 * tig;
        float b0 = bvp[col] + btg[col];
        float b1 = bvp[col + 1] + btg[col + 1];
        float2 p0 = *(const float2*)&pos[(size_t)row0 * HDIM + col];
        float2 p1 = *(const float2*)&pos[(size_t)(row0 + 8) * HDIM + col];
        float2 o0 = make_float2(acc[j][0] + b0 + p0.x, acc[j][1] + b1 + p0.y);
        float2 o1 = make_float2(acc[j][2] + b0 + p1.x, acc[j][3] + b1 + p1.y);
        *(float2*)&g_vis2[(size_t)row0 * HDIM + col] = o0;
        *(float2*)&g_vis2[(size_t)(row0 + 8) * HDIM + col] = o1;
    }
}

// ---------------- K6: language projection + norm (512 thr/blk) -----------
__global__ __launch_bounds__(512) void lang_kernel(const float* __restrict__ lang,
                                                   const float* __restrict__ Wts,
                                                   const float* __restrict__ bts) {
    int b = blockIdx.x, tid = threadIdx.x;   // 512 threads, one output each
    __shared__ float lg[HDIM];
    __shared__ float wr[16];
    lg[tid] = lang[b * HDIM + tid];
    __syncthreads();
    float a = bts[tid];
    #pragma unroll 8
    for (int k = 0; k < HDIM; k++)
        a += lg[k] * Wts[(size_t)k * HDIM + tid];
    g_lang[b * HDIM + tid] = a;
    float q = a * a;
    #pragma unroll
    for (int o = 16; o; o >>= 1) q += __shfl_xor_sync(0xffffffffu, q, o);
    if ((tid & 31) == 0) wr[tid >> 5] = q;
    __syncthreads();
    if (tid < 32) {
        float s = (tid < 16) ? wr[tid] : 0.f;
        #pragma unroll
        for (int o = 8; o; o >>= 1) s += __shfl_xor_sync(0xffffffffu, s, o);
        if (tid == 0) g_ln[b] = sqrtf(s) + EPSF;
    }
}

// ---------------- K7: cosine sim (warp per sel), argmax, box decode ------
__global__ void final_kernel(const float* __restrict__ boxes, float* __restrict__ out) {
    int b = blockIdx.x, tid = threadIdx.x;   // 1024 threads = 32 warps
    int w = tid >> 5, lane = tid & 31;
    __shared__ float ssim[SEL];

    const float4* v2 = (const float4*)(g_vis2 + (size_t)(b * SEL + w) * HDIM);
    const float4* le = (const float4*)(g_lang + (size_t)b * HDIM);
    float d = 0.f, q = 0.f;
    #pragma unroll
    for (int i = 0; i < 4; i++) {
        float4 a = v2[lane + i * 32];
        float4 c = le[lane + i * 32];
        d += a.x * c.x + a.y * c.y + a.z * c.z + a.w * c.w;
        q += a.x * a.x + a.y * a.y + a.z * a.z + a.w * a.w;
    }
    #pragma unroll
    for (int o = 16; o; o >>= 1) {
        d += __shfl_xor_sync(0xffffffffu, d, o);
        q += __shfl_xor_sync(0xffffffffu, q, o);
    }
    if (lane == 0) ssim[w] = d / ((sqrtf(q) + EPSF) * g_ln[b]);
    __syncthreads();

    if (tid < SEL) out[BS * 5 + b * SEL + tid] = ssim[tid];

    if (w == 0) {
        float v = ssim[lane]; int bi = lane;
        #pragma unroll
        for (int o = 16; o; o >>= 1) {
            float ov = __shfl_down_sync(0xffffffffu, v, o);
            int   oi = __shfl_down_sync(0xffffffffu, bi, o);
            if (ov > v || (ov == v && oi < bi)) { v = ov; bi = oi; }
        }
        if (lane == 0) {
            int g = g_idx[b * SEL + bi];
            const float* base = boxes + ((size_t)b * GRID_N + g) * A_N * CH;
            int j = 0; float ov = base[4];
            for (int a = 1; a < A_N; a++) {
                float o2 = base[a * CH + 4];
                if (o2 > ov) { ov = o2; j = a; }
            }
            float x = base[j * CH + 0], y = base[j * CH + 1];
            float wd = base[j * CH + 2], hh = base[j * CH + 3];
            float x1 = x - wd * 0.5f, y1 = y - hh * 0.5f;
            out[b * 5 + 0] = x1;
            out[b * 5 + 1] = y1;
            out[b * 5 + 2] = x1 + wd;
            out[b * 5 + 3] = y1 + hh;
            out[b * 5 + 4] = ov;
        }
    }
}

// ---------------- launch --------------------------------------------------
extern "C" void kernel_launch(void* const* d_in, const int* in_sizes, int n_in,
                              void* d_out, int out_size) {
    const float* boxes    = (const float*)d_in[0];
    const float* x_feat   = (const float*)d_in[1];
    const float* tag_emb  = (const float*)d_in[2];
    const float* pos_emb  = (const float*)d_in[3];
    const float* lang     = (const float*)d_in[4];
    const float* W_vs     = (const float*)d_in[5];
    const float* b_vs     = (const float*)d_in[6];
    const float* W_ts     = (const float*)d_in[7];
    const float* b_ts     = (const float*)d_in[8];
    const float* W_vs_pos = (const float*)d_in[9];
    const float* b_vs_pos = (const float*)d_in[10];
    const float* W_tag    = (const float*)d_in[11];
    const float* b_tag    = (const float*)d_in[12];
    const float* W_soft   = (const float*)d_in[13];
    const float* b_soft   = (const float*)d_in[14];
    float* out = (float*)d_out;

    uint32_t *wvsH, *wvsL, *wvpH, *wvpL, *wtgH, *wtgL;
    cudaGetSymbolAddress((void**)&wvsH, g_WvsH);
    cudaGetSymbolAddress((void**)&wvsL, g_WvsL);
    cudaGetSymbolAddress((void**)&wvpH, g_WvpH);
    cudaGetSymbolAddress((void**)&wvpL, g_WvpL);
    cudaGetSymbolAddress((void**)&wtgH, g_WtgH);
    cudaGetSymbolAddress((void**)&wtgL, g_WtgL);

    topk_kernel<<<BS, 256>>>(boxes);
    gather_kernel<<<BS * SEL, 256>>>(x_feat);
    split_kernel<<<(VDIM * HDIM / 4 + 255) / 256, 256>>>(W_vs, wvsH, wvsL, VDIM * HDIM / 4);
    split_kernel<<<(HDIM * HDIM / 4 + 255) / 256, 256>>>(W_vs_pos, wvpH, wvpL, HDIM * HDIM / 4);
    split_kernel<<<(HDIM * HDIM / 4 + 255) / 256, 256>>>(W_tag, wtgH, wtgL, HDIM * HDIM / 4);
    lang_kernel<<<BS, 512>>>(lang, W_ts, b_ts);
    gemm1_kernel<<<dim3(HDIM / 64, ROWS / 32), 256>>>(b_vs);
    wsoft_kernel<<<ROWS / 4, 256>>>(tag_emb, pos_emb, W_soft, b_soft);
    scale_split_kernel<<<ROWS * HDIM / 4 / 256, 256>>>(tag_emb);
    gemm2_kernel<<<dim3(HDIM / 64, ROWS / 32), 256>>>(b_vs_pos, b_tag, pos_emb);
    final_kernel<<<BS, 1024>>>(boxes, out);
}

// round 11
// speedup vs baseline: 1.2086x; 1.2086x over previous
#include <cuda_runtime.h>
#include <math.h>
#include <stdint.h>

#define BS     32
#define GRID_N 2704
#define A_N    3
#define CH     85
#define VDIM   1024
#define HDIM   512
#define SEL    32
#define ROWS   (BS * SEL)          // 1024 flattened rows
#define EPSF   1e-8f

// ---------------- device scratch (static, no allocation) ----------------
__device__ int   g_idx[BS * SEL];
__device__ float g_isel[(size_t)ROWS * VDIM];
__device__ float g_vis[(size_t)ROWS * HDIM];
__device__ float g_vis2[(size_t)ROWS * HDIM];

// ---------------- tf32 helpers --------------------------------------------
__device__ __forceinline__ uint32_t f2tf(float x) {
    uint32_t r;
    asm("cvt.rna.tf32.f32 %0, %1;" : "=r"(r) : "f"(x));
    return r;
}
__device__ __forceinline__ void split_tf(float x, uint32_t& hi, uint32_t& lo) {
    hi = f2tf(x);
    lo = f2tf(x - __uint_as_float(hi));
}
__device__ __forceinline__ void split4(float4 v, uint4& h, uint4& l) {
    split_tf(v.x, h.x, l.x);
    split_tf(v.y, h.y, l.y);
    split_tf(v.z, h.z, l.z);
    split_tf(v.w, h.w, l.w);
}
__device__ __forceinline__ void mma8(float d[4], const uint32_t a[4], const uint32_t b[2]) {
    asm volatile(
        "mma.sync.aligned.m16n8k8.row.col.f32.tf32.tf32.f32 "
        "{%0,%1,%2,%3}, {%4,%5,%6,%7}, {%8,%9}, {%0,%1,%2,%3};"
        : "+f"(d[0]), "+f"(d[1]), "+f"(d[2]), "+f"(d[3])
        : "r"(a[0]), "r"(a[1]), "r"(a[2]), "r"(a[3]), "r"(b[0]), "r"(b[1]));
}

// ---------------- K1: objectness score + exact top-32 via histogram ------
__global__ void topk_kernel(const float* __restrict__ boxes) {
    int b = blockIdx.x;
    int tid = threadIdx.x;          // 256 threads
    __shared__ float sc[GRID_N];
    __shared__ int   hist[512];
    __shared__ int   s_binB, s_definite;
    __shared__ int   cnt_hi, cnt_cb, overflow;
    __shared__ int   hi_idx[SEL];
    __shared__ float cb_sc[512];
    __shared__ int   cb_idx[512];
    __shared__ int   sel[SEL];
    __shared__ float rv[8];
    __shared__ int   ri[8];

    for (int i = tid; i < 512; i += 256) hist[i] = 0;
    if (tid == 0) { cnt_hi = 0; cnt_cb = 0; overflow = 0; }
    __syncthreads();

    const float* bb = boxes + (size_t)b * GRID_N * A_N * CH;
    for (int g = tid; g < GRID_N; g += 256) {
        const float* p = bb + (size_t)g * A_N * CH;
        float s = (p[4] + p[CH + 4] + p[2 * CH + 4]) * (1.0f / 3.0f);
        sc[g] = s;
        int bin = (int)(s * 512.0f);
        bin = max(0, min(511, bin));
        atomicAdd(&hist[bin], 1);
    }
    __syncthreads();

    if (tid == 0) {
        int cum = 0, bB = 0, def = 0;
        for (int v = 511; v >= 0; v--) {
            cum += hist[v];
            if (cum >= SEL) { bB = v; def = cum - hist[v]; break; }
        }
        s_binB = bB; s_definite = def;
    }
    __syncthreads();
    int binB = s_binB;

    for (int g = tid; g < GRID_N; g += 256) {
        float s = sc[g];
        int bin = (int)(s * 512.0f);
        bin = max(0, min(511, bin));
        if (bin > binB) {
            int p = atomicAdd(&cnt_hi, 1);
            hi_idx[p] = g;
        } else if (bin == binB) {
            int p = atomicAdd(&cnt_cb, 1);
            if (p < 512) { cb_sc[p] = s; cb_idx[p] = g; }
            else overflow = 1;
        }
    }
    __syncthreads();

    if (!overflow) {
        if (tid >= 32 && (tid - 32) < s_definite) sel[tid - 32] = hi_idx[tid - 32];
        if (tid < 32) {
            int need = SEL - s_definite;
            int n = min(cnt_cb, 512);
            for (int it = 0; it < need; it++) {
                float best = -1e30f; int bi = GRID_N;
                for (int c = tid; c < n; c += 32) {
                    float v = cb_sc[c]; int gi = cb_idx[c];
                    if (v > best || (v == best && gi < bi)) { best = v; bi = gi; }
                }
                #pragma unroll
                for (int o = 16; o; o >>= 1) {
                    float ov = __shfl_down_sync(0xffffffffu, best, o);
                    int   oi = __shfl_down_sync(0xffffffffu, bi, o);
                    if (ov > best || (ov == best && oi < bi)) { best = ov; bi = oi; }
                }
                bi = __shfl_sync(0xffffffffu, bi, 0);
                if (tid == 0) sel[s_definite + it] = bi;
                for (int c = tid; c < n; c += 32)
                    if (cb_idx[c] == bi) cb_sc[c] = -1e30f;
                __syncwarp();
            }
        }
    }
    __syncthreads();

    if (overflow) {
        for (int it = 0; it < SEL; it++) {
            float best = -1e30f;
            int   bi = GRID_N;
            for (int g = tid; g < GRID_N; g += 256) {
                float v = sc[g];
                if (v > best) { best = v; bi = g; }
            }
            #pragma unroll
            for (int o = 16; o; o >>= 1) {
                float ov = __shfl_down_sync(0xffffffffu, best, o);
                int   oi = __shfl_down_sync(0xffffffffu, bi, o);
                if (ov > best || (ov == best && oi < bi)) { best = ov; bi = oi; }
            }
            if ((tid & 31) == 0) { rv[tid >> 5] = best; ri[tid >> 5] = bi; }
            __syncthreads();
            if (tid == 0) {
                float B = rv[0]; int BI = ri[0];
                for (int w = 1; w < 8; w++)
                    if (rv[w] > B || (rv[w] == B && ri[w] < BI)) { B = rv[w]; BI = ri[w]; }
                sel[it] = BI;
                sc[BI] = -1e30f;
            }
            __syncthreads();
        }
    }

    if (tid == 0) {
        for (int i = 1; i < SEL; i++) {
            int v = sel[i], j = i - 1;
            while (j >= 0 && sel[j] > v) { sel[j + 1] = sel[j]; j--; }
            sel[j + 1] = v;
        }
        for (int i = 0; i < SEL; i++) g_idx[b * SEL + i] = sel[i];
    }
}

// ---------------- K2: gather selected feature columns --------------------
__global__ void gather_kernel(const float* __restrict__ xfeat) {
    int row = blockIdx.x;           // b*SEL + s
    int b = row >> 5;
    int g = g_idx[row];
    const float* src = xfeat + (size_t)b * VDIM * GRID_N + g;
    float* dst = g_isel + (size_t)row * VDIM;
    for (int v = threadIdx.x; v < VDIM; v += blockDim.x)
        dst[v] = __ldg(&src[(size_t)v * GRID_N]);
}

// ---------------- K3: vis = isel @ W_vs + b_vs (3xTF32) ------------------
// Tile 32(M)x64(N), BK=32, 256 threads = 8 warps (2m x 4n), warp m16n16.
// A and B both split to tf32 hi/lo planes AT STS -> inner loop pure LDS+MMA.
// A planes: [m][k] stride 36. B planes: [k][n] swizzle n ^ ((k&3)*8).
#define G1_BK 32
#define G1_NT (VDIM / G1_BK)
#define X1ST 36
__global__ __launch_bounds__(256) void gemm1_kernel(const float* __restrict__ W,
                                                    const float* __restrict__ bias) {
    int mBase = blockIdx.y * 32;
    int nBase = blockIdx.x * 64;
    int tid = threadIdx.x;
    int warp = tid >> 5, lane = tid & 31;
    int gid = lane >> 2, tig = lane & 3;
    int wm = (warp & 1) * 16, wn = (warp >> 1) * 16;

    __shared__ __align__(16) uint32_t AsH[2][32 * X1ST];
    __shared__ __align__(16) uint32_t AsL[2][32 * X1ST];
    __shared__ __align__(16) uint32_t WsH[2][G1_BK * 64];
    __shared__ __align__(16) uint32_t WsL[2][G1_BK * 64];

    int a_m = tid >> 3;             // 0..31
    int a_k = (tid & 7) * 4;        // 0..28
    int w_k = tid >> 4;             // 0..15 (k rows w_k, w_k+16)
    int w_n = (tid & 15) * 4;

    const float* Ab = g_isel + (size_t)mBase * VDIM;

    float4 rA, rW[2];
    rA = *(const float4*)&Ab[(size_t)a_m * VDIM + a_k];
    #pragma unroll
    for (int i = 0; i < 2; i++)
        rW[i] = *(const float4*)&W[(size_t)(w_k + i * 16) * HDIM + nBase + w_n];

    {
        uint4 h, l;
        split4(rA, h, l);
        *(uint4*)&AsH[0][a_m * X1ST + a_k] = h;
        *(uint4*)&AsL[0][a_m * X1ST + a_k] = l;
        #pragma unroll
        for (int i = 0; i < 2; i++) {
            int k = w_k + i * 16;
            int off = k * 64 + (w_n ^ ((k & 3) * 8));
            split4(rW[i], h, l);
            *(uint4*)&WsH[0][off] = h;
            *(uint4*)&WsL[0][off] = l;
        }
    }
    __syncthreads();

    float acc[2][4];
    #pragma unroll
    for (int j = 0; j < 2; j++)
        #pragma unroll
        for (int r = 0; r < 4; r++) acc[j][r] = 0.f;

    for (int t = 0; t < G1_NT; t++) {
        int cur = t & 1;
        int k0n = (t + 1) * G1_BK;
        if (t + 1 < G1_NT) {
            rA = *(const float4*)&Ab[(size_t)a_m * VDIM + k0n + a_k];
            #pragma unroll
            for (int i = 0; i < 2; i++)
                rW[i] = *(const float4*)&W[(size_t)(k0n + w_k + i * 16) * HDIM + nBase + w_n];
        }
        #pragma unroll
        for (int kb = 0; kb < G1_BK; kb += 8) {
            uint32_t ah[4], al[4];
            ah[0] = AsH[cur][(wm + gid) * X1ST + kb + tig];
            ah[1] = AsH[cur][(wm + gid + 8) * X1ST + kb + tig];
            ah[2] = AsH[cur][(wm + gid) * X1ST + kb + tig + 4];
            ah[3] = AsH[cur][(wm + gid + 8) * X1ST + kb + tig + 4];
            al[0] = AsL[cur][(wm + gid) * X1ST + kb + tig];
            al[1] = AsL[cur][(wm + gid + 8) * X1ST + kb + tig];
            al[2] = AsL[cur][(wm + gid) * X1ST + kb + tig + 4];
            al[3] = AsL[cur][(wm + gid + 8) * X1ST + kb + tig + 4];
            #pragma unroll
            for (int j = 0; j < 2; j++) {
                int n0 = wn + j * 8;
                int sw = (n0 + gid) ^ (tig * 8);
                uint32_t bh[2], bl[2];
                bh[0] = WsH[cur][(kb + tig) * 64 + sw];
                bh[1] = WsH[cur][(kb + tig + 4) * 64 + sw];
                bl[0] = WsL[cur][(kb + tig) * 64 + sw];
                bl[1] = WsL[cur][(kb + tig + 4) * 64 + sw];
                mma8(acc[j], ah, bh);
                mma8(acc[j], ah, bl);
                mma8(acc[j], al, bh);
            }
        }
        if (t + 1 < G1_NT) {
            int nx = cur ^ 1;
            uint4 h, l;
            split4(rA, h, l);
            *(uint4*)&AsH[nx][a_m * X1ST + a_k] = h;
            *(uint4*)&AsL[nx][a_m * X1ST + a_k] = l;
            #pragma unroll
            for (int i = 0; i < 2; i++) {
                int k = w_k + i * 16;
                int off = k * 64 + (w_n ^ ((k & 3) * 8));
                split4(rW[i], h, l);
                *(uint4*)&WsH[nx][off] = h;
                *(uint4*)&WsL[nx][off] = l;
            }
        }
        __syncthreads();
    }

    int row0 = mBase + wm + gid;
    #pragma unroll
    for (int j = 0; j < 2; j++) {
        int col = nBase + wn + j * 8 + 2 * tig;
        float b0 = bias[col], b1 = bias[col + 1];
        float2 o0 = make_float2(acc[j][0] + b0, acc[j][1] + b1);
        float2 o1 = make_float2(acc[j][2] + b0, acc[j][3] + b1);
        *(float2*)&g_vis[(size_t)row0 * HDIM + col] = o0;
        *(float2*)&g_vis[(size_t)(row0 + 8) * HDIM + col] = o1;
    }
}

// ---------------- K4: vis2 dual GEMM (3xTF32) with FUSED gate compute ----
// Tile 32x64, BK=16, 256 threads = 8 warps, warp m16n16.
// Prologue: each warp computes log-softmax gates for 4 of the block's 32
// rows (8x redundant across nBase blocks; ~1us). X/Y scaled+split at STS.
#define G2_BK 16
#define G2_NT (HDIM / G2_BK)
#define A2ST 20
__global__ __launch_bounds__(256) void gemm2_kernel(
    const float* __restrict__ Wvp, const float* __restrict__ bvp,
    const float* __restrict__ Wtg, const float* __restrict__ btg,
    const float* __restrict__ tag, const float* __restrict__ pos,
    const float* __restrict__ Wsoft, const float* __restrict__ bsoft) {
    int mBase = blockIdx.y * 32;
    int nBase = blockIdx.x * 64;
    int tid = threadIdx.x;
    int warp = tid >> 5, lane = tid & 31;
    int gid = lane >> 2, tig = lane & 3;
    int wm = (warp & 1) * 16, wn = (warp >> 1) * 16;

    __shared__ __align__(16) uint32_t XsH[2][32 * A2ST];
    __shared__ __align__(16) uint32_t XsL[2][32 * A2ST];
    __shared__ __align__(16) uint32_t YsH[2][32 * A2ST];
    __shared__ __align__(16) uint32_t YsL[2][32 * A2ST];
    __shared__ __align__(16) uint32_t WsH[2][G2_BK * 64];
    __shared__ __align__(16) uint32_t WsL[2][G2_BK * 64];
    __shared__ __align__(16) uint32_t VsH[2][G2_BK * 64];
    __shared__ __align__(16) uint32_t VsL[2][G2_BK * 64];
    __shared__ float w0s[32], w1s[32];

    // ---- fused gate computation: warp w -> rows w*4 .. w*4+3 ----
    {
        const float4* Wq = (const float4*)Wsoft;
        #pragma unroll
        for (int rr = 0; rr < 4; rr++) {
            int rloc = warp * 4 + rr;
            int row = mBase + rloc;
            const float4* v = (const float4*)(g_vis + (size_t)row * HDIM);
            const float4* t4 = (const float4*)(tag + (size_t)row * HDIM);
            const float4* p4 = (const float4*)(pos + (size_t)row * HDIM);
            float l0 = 0.f, l1 = 0.f;
            #pragma unroll
            for (int i = 0; i < 4; i++) {
                int h4 = i * 32 + lane;
                float4 a = v[h4], c = t4[h4], e = p4[h4];
                float s0 = a.x + c.x + e.x, s1 = a.y + c.y + e.y;
                float s2 = a.z + c.z + e.z, s3 = a.w + c.w + e.w;
                float4 w01 = Wq[h4 * 2], w23 = Wq[h4 * 2 + 1];
                l0 += s0 * w01.x + s1 * w01.z + s2 * w23.x + s3 * w23.z;
                l1 += s0 * w01.y + s1 * w01.w + s2 * w23.y + s3 * w23.w;
            }
            #pragma unroll
            for (int o = 16; o; o >>= 1) {
                l0 += __shfl_xor_sync(0xffffffffu, l0, o);
                l1 += __shfl_xor_sync(0xffffffffu, l1, o);
            }
            if (lane == 0) {
                l0 = (l0 + bsoft[0]) / 0.03f;
                l1 = (l1 + bsoft[1]) / 0.03f;
                float m = fmaxf(l0, l1);
                float lse = m + logf(expf(l0 - m) + expf(l1 - m));
                w0s[rloc] = l0 - lse;
                w1s[rloc] = l1 - lse;
            }
        }
    }
    __syncthreads();

    // A-side: threads 0-127 handle X(=vis*w0), 128-255 handle Y(=tag*w1)
    int ahalf = tid >> 7;
    int at = tid & 127;
    int a_m = at >> 2;              // 0..31
    int a_k = (at & 3) * 4;         // 0..12
    int w_k = tid >> 4;             // 0..15
    int w_n = (tid & 15) * 4;

    const float* Ain = (ahalf ? tag + (size_t)mBase * HDIM
                              : g_vis + (size_t)mBase * HDIM);
    float myw = ahalf ? w1s[a_m] : w0s[a_m];

    float4 rS, rW, rV;
    rS = *(const float4*)&Ain[(size_t)a_m * HDIM + a_k];
    rW = *(const float4*)&Wvp[(size_t)w_k * HDIM + nBase + w_n];
    rV = *(const float4*)&Wtg[(size_t)w_k * HDIM + nBase + w_n];

    {
        float4 s = rS;
        s.x *= myw; s.y *= myw; s.z *= myw; s.w *= myw;
        uint4 h, l;
        split4(s, h, l);
        uint32_t* dH = (ahalf ? YsH[0] : XsH[0]) + a_m * A2ST + a_k;
        uint32_t* dL = (ahalf ? YsL[0] : XsL[0]) + a_m * A2ST + a_k;
        *(uint4*)dH = h;
        *(uint4*)dL = l;
        int off = w_k * 64 + (w_n ^ ((w_k & 3) * 8));
        split4(rW, h, l);
        *(uint4*)&WsH[0][off] = h;
        *(uint4*)&WsL[0][off] = l;
        split4(rV, h, l);
        *(uint4*)&VsH[0][off] = h;
        *(uint4*)&VsL[0][off] = l;
    }
    __syncthreads();

    float acc[2][4];
    #pragma unroll
    for (int j = 0; j < 2; j++)
        #pragma unroll
        for (int r = 0; r < 4; r++) acc[j][r] = 0.f;

    for (int t = 0; t < G2_NT; t++) {
        int cur = t & 1;
        int k0n = (t + 1) * G2_BK;
        if (t + 1 < G2_NT) {
            rS = *(const float4*)&Ain[(size_t)a_m * HDIM + k0n + a_k];
            rW = *(const float4*)&Wvp[(size_t)(k0n + w_k) * HDIM + nBase + w_n];
            rV = *(const float4*)&Wtg[(size_t)(k0n + w_k) * HDIM + nBase + w_n];
        }
        #pragma unroll
        for (int kb = 0; kb < G2_BK; kb += 8) {
            uint32_t xh[4], xl[4], yh[4], yl[4];
            xh[0] = XsH[cur][(wm + gid) * A2ST + kb + tig];
            xh[1] = XsH[cur][(wm + gid + 8) * A2ST + kb + tig];
            xh[2] = XsH[cur][(wm + gid) * A2ST + kb + tig + 4];
            xh[3] = XsH[cur][(wm + gid + 8) * A2ST + kb + tig + 4];
            xl[0] = XsL[cur][(wm + gid) * A2ST + kb + tig];
            xl[1] = XsL[cur][(wm + gid + 8) * A2ST + kb + tig];
            xl[2] = XsL[cur][(wm + gid) * A2ST + kb + tig + 4];
            xl[3] = XsL[cur][(wm + gid + 8) * A2ST + kb + tig + 4];
            yh[0] = YsH[cur][(wm + gid) * A2ST + kb + tig];
            yh[1] = YsH[cur][(wm + gid + 8) * A2ST + kb + tig];
            yh[2] = YsH[cur][(wm + gid) * A2ST + kb + tig + 4];
            yh[3] = YsH[cur][(wm + gid + 8) * A2ST + kb + tig + 4];
            yl[0] = YsL[cur][(wm + gid) * A2ST + kb + tig];
            yl[1] = YsL[cur][(wm + gid + 8) * A2ST + kb + tig];
            yl[2] = YsL[cur][(wm + gid) * A2ST + kb + tig + 4];
            yl[3] = YsL[cur][(wm + gid + 8) * A2ST + kb + tig + 4];
            #pragma unroll
            for (int j = 0; j < 2; j++) {
                int n0 = wn + j * 8;
                int sw = (n0 + gid) ^ (tig * 8);
                uint32_t wh[2], wl[2], vh[2], vl[2];
                wh[0] = WsH[cur][(kb + tig) * 64 + sw];
                wh[1] = WsH[cur][(kb + tig + 4) * 64 + sw];
                wl[0] = WsL[cur][(kb + tig) * 64 + sw];
                wl[1] = WsL[cur][(kb + tig + 4) * 64 + sw];
                vh[0] = VsH[cur][(kb + tig) * 64 + sw];
                vh[1] = VsH[cur][(kb + tig + 4) * 64 + sw];
                vl[0] = VsL[cur][(kb + tig) * 64 + sw];
                vl[1] = VsL[cur][(kb + tig + 4) * 64 + sw];
                mma8(acc[j], xh, wh);
                mma8(acc[j], xh, wl);
                mma8(acc[j], xl, wh);
                mma8(acc[j], yh, vh);
                mma8(acc[j], yh, vl);
                mma8(acc[j], yl, vh);
            }
        }
        if (t + 1 < G2_NT) {
            int nx = cur ^ 1;
            float4 s = rS;
            s.x *= myw; s.y *= myw; s.z *= myw; s.w *= myw;
            uint4 h, l;
            split4(s, h, l);
            uint32_t* dH = (ahalf ? YsH[nx] : XsH[nx]) + a_m * A2ST + a_k;
            uint32_t* dL = (ahalf ? YsL[nx] : XsL[nx]) + a_m * A2ST + a_k;
            *(uint4*)dH = h;
            *(uint4*)dL = l;
            int off = w_k * 64 + (w_n ^ ((w_k & 3) * 8));
            split4(rW, h, l);
            *(uint4*)&WsH[nx][off] = h;
            *(uint4*)&WsL[nx][off] = l;
            split4(rV, h, l);
            *(uint4*)&VsH[nx][off] = h;
            *(uint4*)&VsL[nx][off] = l;
        }
        __syncthreads();
    }

    int row0 = mBase + wm + gid;
    #pragma unroll
    for (int j = 0; j < 2; j++) {
        int col = nBase + wn + j * 8 + 2 * tig;
        float b0 = bvp[col] + btg[col];
        float b1 = bvp[col + 1] + btg[col + 1];
        float2 p0 = *(const float2*)&pos[(size_t)row0 * HDIM + col];
        float2 p1 = *(const float2*)&pos[(size_t)(row0 + 8) * HDIM + col];
        float2 o0 = make_float2(acc[j][0] + b0 + p0.x, acc[j][1] + b1 + p0.y);
        float2 o1 = make_float2(acc[j][2] + b0 + p1.x, acc[j][3] + b1 + p1.y);
        *(float2*)&g_vis2[(size_t)row0 * HDIM + col] = o0;
        *(float2*)&g_vis2[(size_t)(row0 + 8) * HDIM + col] = o1;
    }
}

// ---------------- K5: FUSED lang proj + cosine sim + argmax + box --------
__global__ __launch_bounds__(1024) void final_kernel(
    const float* __restrict__ boxes, const float* __restrict__ lang,
    const float* __restrict__ Wts, const float* __restrict__ bts,
    float* __restrict__ out) {
    int b = blockIdx.x, tid = threadIdx.x;   // 1024 threads = 32 warps
    int w = tid >> 5, lane = tid & 31;
    __shared__ float lg[HDIM];
    __shared__ float le[HDIM];
    __shared__ float part[1024];
    __shared__ float wr[16];
    __shared__ float ssim[SEL];
    __shared__ float s_ln;

    // ---- language projection (split-K over 1024 threads) ----
    if (tid < HDIM) lg[tid] = lang[b * HDIM + tid];
    __syncthreads();
    {
        int h = tid & (HDIM - 1);
        int khalf = tid >> 9;                // 0 or 1
        int k0 = khalf * (HDIM / 2);
        float a = 0.f;
        #pragma unroll 8
        for (int k = 0; k < HDIM / 2; k++)
            a += lg[k0 + k] * Wts[(size_t)(k0 + k) * HDIM + h];
        part[tid] = a;
    }
    __syncthreads();
    if (tid < HDIM) le[tid] = part[tid] + part[tid + HDIM] + bts[tid];
    __syncthreads();
    // ---- norm of le ----
    if (tid < HDIM) {
        float q = le[tid] * le[tid];
        #pragma unroll
        for (int o = 16; o; o >>= 1) q += __shfl_xor_sync(0xffffffffu, q, o);
        if (lane == 0) wr[w] = q;
    }
    __syncthreads();
    if (tid == 0) {
        float s = 0.f;
        #pragma unroll
        for (int i = 0; i < 16; i++) s += wr[i];
        s_ln = sqrtf(s) + EPSF;
    }
    __syncthreads();

    // ---- cosine sim: warp per selection ----
    const float4* v2 = (const float4*)(g_vis2 + (size_t)(b * SEL + w) * HDIM);
    const float4* lef = (const float4*)le;
    float d = 0.f, q = 0.f;
    #pragma unroll
    for (int i = 0; i < 4; i++) {
        float4 a = v2[lane + i * 32];
        float4 c = lef[lane + i * 32];
        d += a.x * c.x + a.y * c.y + a.z * c.z + a.w * c.w;
        q += a.x * a.x + a.y * a.y + a.z * a.z + a.w * a.w;
    }
    #pragma unroll
    for (int o = 16; o; o >>= 1) {
        d += __shfl_xor_sync(0xffffffffu, d, o);
        q += __shfl_xor_sync(0xffffffffu, q, o);
    }
    if (lane == 0) ssim[w] = d / ((sqrtf(q) + EPSF) * s_ln);
    __syncthreads();

    if (tid < SEL) out[BS * 5 + b * SEL + tid] = ssim[tid];

    if (w == 0) {
        float v = ssim[lane]; int bi = lane;
        #pragma unroll
        for (int o = 16; o; o >>= 1) {
            float ov = __shfl_down_sync(0xffffffffu, v, o);
            int   oi = __shfl_down_sync(0xffffffffu, bi, o);
            if (ov > v || (ov == v && oi < bi)) { v = ov; bi = oi; }
        }
        if (lane == 0) {
            int g = g_idx[b * SEL + bi];
            const float* base = boxes + ((size_t)b * GRID_N + g) * A_N * CH;
            int j = 0; float ov = base[4];
            for (int a = 1; a < A_N; a++) {
                float o2 = base[a * CH + 4];
                if (o2 > ov) { ov = o2; j = a; }
            }
            float x = base[j * CH + 0], y = base[j * CH + 1];
            float wd = base[j * CH + 2], hh = base[j * CH + 3];
            float x1 = x - wd * 0.5f, y1 = y - hh * 0.5f;
            out[b * 5 + 0] = x1;
            out[b * 5 + 1] = y1;
            out[b * 5 + 2] = x1 + wd;
            out[b * 5 + 3] = y1 + hh;
            out[b * 5 + 4] = ov;
        }
    }
}

// ---------------- launch --------------------------------------------------
extern "C" void kernel_launch(void* const* d_in, const int* in_sizes, int n_in,
                              void* d_out, int out_size) {
    const float* boxes    = (const float*)d_in[0];
    const float* x_feat   = (const float*)d_in[1];
    const float* tag_emb  = (const float*)d_in[2];
    const float* pos_emb  = (const float*)d_in[3];
    const float* lang     = (const float*)d_in[4];
    const float* W_vs     = (const float*)d_in[5];
    const float* b_vs     = (const float*)d_in[6];
    const float* W_ts     = (const float*)d_in[7];
    const float* b_ts     = (const float*)d_in[8];
    const float* W_vs_pos = (const float*)d_in[9];
    const float* b_vs_pos = (const float*)d_in[10];
    const float* W_tag    = (const float*)d_in[11];
    const float* b_tag    = (const float*)d_in[12];
    const float* W_soft   = (const float*)d_in[13];
    const float* b_soft   = (const float*)d_in[14];
    float* out = (float*)d_out;

    topk_kernel<<<BS, 256>>>(boxes);
    gather_kernel<<<BS * SEL, 256>>>(x_feat);
    gemm1_kernel<<<dim3(HDIM / 64, ROWS / 32), 256>>>(W_vs, b_vs);
    gemm2_kernel<<<dim3(HDIM / 64, ROWS / 32), 256>>>(W_vs_pos, b_vs_pos, W_tag, b_tag,
                                                      tag_emb, pos_emb, W_soft, b_soft);
    final_kernel<<<BS, 1024>>>(boxes, lang, W_ts, b_ts, out);
}